// round 6
// baseline (speedup 1.0000x reference)
#include <cuda_runtime.h>
#include <cuda_bf16.h>

// WeightedAverage: out = sum_{3x3} v*exp(-v) / sum_{3x3} exp(-v)
// (softmax(-(local - x^2)) == softmax(-local): x^2 constant over patch axis;
//  zero padding contributes w=1 to denom, 0 to numer == loading v=0 OOB.)
//
// Lane owns float4 (4 cols); warp covers 128 cols, sweeps 48 rows.
// 4-slot raw register ring, loads 2 rows ahead; vertical 3-sum via 2-term
// sliding recurrence. regs<=48 -> 5 blocks/SM -> capacity 740 blocks/wave.
// SROWS=48 -> grid = 12*4*16 = 768 blocks = 1.04 waves (runtime here is
// n_waves * T_CTA; single wave is the dominant lever, per R4/R5 data).

#define IMG_W 1536
#define IMG_H 1536
#define SROWS 48
#define WPB   8

__device__ __forceinline__ float4 f4add(const float4 a, const float4 b) {
    return make_float4(a.x + b.x, a.y + b.y, a.z + b.z, a.w + b.w);
}

__global__ __launch_bounds__(256, 5)
void wavg_kernel(const float* __restrict__ x, float* __restrict__ out) {
    const int lane = threadIdx.x & 31;
    const int wrp  = threadIdx.x >> 5;
    const int col0 = blockIdx.x * 128 + lane * 4;
    const int y0   = (blockIdx.y * WPB + wrp) * SROWS;
    const size_t ibase = (size_t)blockIdx.z * (size_t)(IMG_W * IMG_H);
    const float* __restrict__ img = x + ibase;
    float* __restrict__ optr = out + ibase + (size_t)y0 * IMG_W + col0;

    const bool has_l = (col0 > 0);
    const bool has_r = (col0 + 4 < IMG_W);

    float4 raw[4];

    auto load4 = [&](int y) -> float4 {
        if ((unsigned)y < (unsigned)IMG_H)
            return __ldg(reinterpret_cast<const float4*>(img + (size_t)y * IMG_W + col0));
        return make_float4(0.f, 0.f, 0.f, 0.f);
    };

    // Horizontal 3-sums of w=exp(-v) and wv for one row.
    auto hsum = [&](int y, const float4& v, float4& w, float4& wv) {
        float vl = 0.f, vr = 0.f;
        if ((unsigned)y < (unsigned)IMG_H) {
            const float* p = img + (size_t)y * IMG_W + col0;
            if (has_l) vl = __ldg(p - 1);
            if (has_r) vr = __ldg(p + 4);
        }
        const float w0 = __expf(-v.x);
        const float w1 = __expf(-v.y);
        const float w2 = __expf(-v.z);
        const float w3 = __expf(-v.w);
        const float wl = __expf(-vl);
        const float wr = __expf(-vr);
        w.x = wl + w0 + w1;
        w.y = w0 + w1 + w2;
        w.z = w1 + w2 + w3;
        w.w = w2 + w3 + wr;
        const float al = wl * vl,  a0 = w0 * v.x, a1 = w1 * v.y;
        const float a2 = w2 * v.z, a3 = w3 * v.w, ar = wr * vr;
        wv.x = al + a0 + a1;
        wv.y = a0 + a1 + a2;
        wv.z = a1 + a2 + a3;
        wv.w = a2 + a3 + ar;
    };

    // Prologue: rows y0-1 .. y0+2 in flight (slot(row) = (row-y0+1)&3).
    raw[0] = load4(y0 - 1);
    raw[1] = load4(y0);
    raw[2] = load4(y0 + 1);
    raw[3] = load4(y0 + 2);

    float4 hw0, hv0, hw1, hv1;
    hsum(y0 - 1, raw[0], hw0, hv0);
    hsum(y0,     raw[1], hw1, hv1);
    float4 Aw  = f4add(hw0, hw1), Bw  = hw1;    // A = h(-1)+h(0), B = h(0)
    float4 Awv = f4add(hv0, hv1), Bwv = hv1;

    #pragma unroll 8
    for (int k = 0; k < SROWS; k++) {
        // Prefetch row y0+k+3 into the slot freed by row y0+k-1.
        if (k < SROWS - 2)
            raw[k & 3] = load4(y0 + k + 3);
        // h-sum row y0+k+1 (its float4 loaded 2 iterations ago).
        float4 hw, hv;
        hsum(y0 + k + 1, raw[(k + 2) & 3], hw, hv);

        const float4 den = f4add(Aw,  hw);
        const float4 num = f4add(Awv, hv);
        float4 o;
        o.x = __fdividef(num.x, den.x);
        o.y = __fdividef(num.y, den.y);
        o.z = __fdividef(num.z, den.z);
        o.w = __fdividef(num.w, den.w);
        __stcs(reinterpret_cast<float4*>(optr), o);
        optr += IMG_W;

        Aw  = f4add(Bw,  hw);  Bw  = hw;
        Awv = f4add(Bwv, hv);  Bwv = hv;
    }
}

extern "C" void kernel_launch(void* const* d_in, const int* in_sizes, int n_in,
                              void* d_out, int out_size) {
    const float* x = (const float*)d_in[0];
    float* out = (float*)d_out;
    dim3 grid(IMG_W / 128, IMG_H / (WPB * SROWS), 16);
    wavg_kernel<<<grid, WPB * 32>>>(x, out);
}

// round 7
// speedup vs baseline: 1.6619x; 1.6619x over previous
#include <cuda_runtime.h>
#include <cuda_bf16.h>

// WeightedAverage: out = sum_{3x3} v*exp(-v) / sum_{3x3} exp(-v)
// (softmax(-(local - x^2)) == softmax(-local): x^2 constant over patch axis;
//  zero padding contributes w=1 to denom, 0 to numer == loading v=0 OOB.)
//
// Grid-decoupled tiling: 2304 tiles of 128x128 (8 warps x 16 rows), exactly
// 576 blocks x 4 tiles each. 576 blocks < 740 (=148 SM x 5 blk @ 48 regs)
// -> single resident wave, no wave transitions, no tail (R4/R5/R6 showed
// runtime here = waves x T_CTA; this kills the wave term).
// Inner sweep FULLY unrolled (R6 showed partial unroll collapses MLP):
// 4-slot raw float4 ring, loads 2 rows ahead; vertical 3-sum recurrence.

#define IMG_W   1536
#define IMG_H   1536
#define SROWS   16
#define WPB     8
#define TILES_X 12
#define TILES_Y 12
#define N_IMG   16
#define N_TILES (TILES_X * TILES_Y * N_IMG)   // 2304
#define NBLK    576                           // 4 tiles per block

__device__ __forceinline__ float4 f4add(const float4 a, const float4 b) {
    return make_float4(a.x + b.x, a.y + b.y, a.z + b.z, a.w + b.w);
}

__global__ __launch_bounds__(256, 5)
void wavg_kernel(const float* __restrict__ x, float* __restrict__ out) {
    const int lane = threadIdx.x & 31;
    const int wrp  = threadIdx.x >> 5;

    #pragma unroll 1
    for (int t = blockIdx.x; t < N_TILES; t += NBLK) {
        const int img_i = t / (TILES_X * TILES_Y);
        const int rem   = t - img_i * (TILES_X * TILES_Y);
        const int ty    = rem / TILES_X;
        const int tx    = rem - ty * TILES_X;

        const int col0 = tx * 128 + lane * 4;
        const int y0   = ty * 128 + wrp * SROWS;
        const size_t ibase = (size_t)img_i * (size_t)(IMG_W * IMG_H);
        const float* __restrict__ img = x + ibase;
        float* __restrict__ optr = out + ibase + (size_t)y0 * IMG_W + col0;

        const bool has_l = (col0 > 0);
        const bool has_r = (col0 + 4 < IMG_W);

        float4 raw[4];

        auto load4 = [&](int y) -> float4 {
            if ((unsigned)y < (unsigned)IMG_H)
                return __ldg(reinterpret_cast<const float4*>(img + (size_t)y * IMG_W + col0));
            return make_float4(0.f, 0.f, 0.f, 0.f);
        };

        // Horizontal 3-sums of w=exp(-v) and wv for one row.
        auto hsum = [&](int y, const float4& v, float4& w, float4& wv) {
            float vl = 0.f, vr = 0.f;
            if ((unsigned)y < (unsigned)IMG_H) {
                const float* p = img + (size_t)y * IMG_W + col0;
                if (has_l) vl = __ldg(p - 1);
                if (has_r) vr = __ldg(p + 4);
            }
            const float w0 = __expf(-v.x);
            const float w1 = __expf(-v.y);
            const float w2 = __expf(-v.z);
            const float w3 = __expf(-v.w);
            const float wl = __expf(-vl);
            const float wr = __expf(-vr);
            w.x = wl + w0 + w1;
            w.y = w0 + w1 + w2;
            w.z = w1 + w2 + w3;
            w.w = w2 + w3 + wr;
            const float al = wl * vl,  a0 = w0 * v.x, a1 = w1 * v.y;
            const float a2 = w2 * v.z, a3 = w3 * v.w, ar = wr * vr;
            wv.x = al + a0 + a1;
            wv.y = a0 + a1 + a2;
            wv.z = a1 + a2 + a3;
            wv.w = a2 + a3 + ar;
        };

        // Prologue: rows y0-1 .. y0+2 in flight (slot(row) = (row-y0+1)&3).
        raw[0] = load4(y0 - 1);
        raw[1] = load4(y0);
        raw[2] = load4(y0 + 1);
        raw[3] = load4(y0 + 2);

        float4 hw0, hv0, hw1, hv1;
        hsum(y0 - 1, raw[0], hw0, hv0);
        hsum(y0,     raw[1], hw1, hv1);
        float4 Aw  = f4add(hw0, hw1), Bw  = hw1;   // A = h(-1)+h(0), B = h(0)
        float4 Awv = f4add(hv0, hv1), Bwv = hv1;

        #pragma unroll
        for (int k = 0; k < SROWS; k++) {
            // Prefetch row y0+k+3 into the slot freed by row y0+k-1.
            if (k < SROWS - 2)
                raw[k & 3] = load4(y0 + k + 3);
            // h-sum row y0+k+1 (its float4 loaded 2 iterations ago).
            float4 hw, hv;
            hsum(y0 + k + 1, raw[(k + 2) & 3], hw, hv);

            const float4 den = f4add(Aw,  hw);
            const float4 num = f4add(Awv, hv);
            float4 o;
            o.x = __fdividef(num.x, den.x);
            o.y = __fdividef(num.y, den.y);
            o.z = __fdividef(num.z, den.z);
            o.w = __fdividef(num.w, den.w);
            __stcs(reinterpret_cast<float4*>(optr), o);
            optr += IMG_W;

            Aw  = f4add(Bw,  hw);  Bw  = hw;
            Awv = f4add(Bwv, hv);  Bwv = hv;
        }
    }
}

extern "C" void kernel_launch(void* const* d_in, const int* in_sizes, int n_in,
                              void* d_out, int out_size) {
    const float* x = (const float*)d_in[0];
    float* out = (float*)d_out;
    wavg_kernel<<<NBLK, WPB * 32>>>(x, out);
}

// round 8
// speedup vs baseline: 2.0779x; 1.2503x over previous
#include <cuda_runtime.h>
#include <cuda_bf16.h>

// WeightedAverage: out = sum_{3x3} v*exp(-v) / sum_{3x3} exp(-v)
// (softmax(-(local - x^2)) == softmax(-local): x^2 constant over patch axis;
//  zero padding contributes w=1 to denom, 0 to numer == loading v=0 OOB.)
//
// 2304 tiles of 128x128 (8 warps x 16 rows), grid = 592 = 148x4 blocks,
// grid-stride (single resident wave, 4 blocks/SM everywhere).
// Ring of 3 slots {float4 v, float vl, float vr}: vector AND halo scalars
// all prefetched 2 rows ahead -> steady-state loop has zero load->use
// dependencies (R7 showed consume-time halo LDGs were the exposed latency).
// Sweep fully unrolled (R6: partial unroll collapses MLP).

#define IMG_W   1536
#define IMG_H   1536
#define SROWS   16
#define WPB     8
#define TILES_X 12
#define TILES_Y 12
#define N_IMG   16
#define N_TILES (TILES_X * TILES_Y * N_IMG)   // 2304
#define NBLK    592                           // 148 SM x 4 blocks

struct Slot { float4 v; float vl, vr; };

__device__ __forceinline__ float4 f4add(const float4 a, const float4 b) {
    return make_float4(a.x + b.x, a.y + b.y, a.z + b.z, a.w + b.w);
}

__global__ __launch_bounds__(256, 4)
void wavg_kernel(const float* __restrict__ x, float* __restrict__ out) {
    const int lane = threadIdx.x & 31;
    const int wrp  = threadIdx.x >> 5;

    #pragma unroll 1
    for (int t = blockIdx.x; t < N_TILES; t += NBLK) {
        const int img_i = t / (TILES_X * TILES_Y);
        const int rem   = t - img_i * (TILES_X * TILES_Y);
        const int ty    = rem / TILES_X;
        const int tx    = rem - ty * TILES_X;

        const int col0 = tx * 128 + lane * 4;
        const int y0   = ty * 128 + wrp * SROWS;
        const size_t ibase = (size_t)img_i * (size_t)(IMG_W * IMG_H);
        const float* __restrict__ img = x + ibase;
        float* __restrict__ optr = out + ibase + (size_t)y0 * IMG_W + col0;

        const bool has_l = (col0 > 0);
        const bool has_r = (col0 + 4 < IMG_W);

        Slot ring[3];

        // Load row y: float4 plus both halo scalars, together.
        auto loadrow = [&](int y) -> Slot {
            Slot s;
            s.v = make_float4(0.f, 0.f, 0.f, 0.f);
            s.vl = 0.f; s.vr = 0.f;
            if ((unsigned)y < (unsigned)IMG_H) {
                const float* p = img + (size_t)y * IMG_W + col0;
                s.v = __ldg(reinterpret_cast<const float4*>(p));
                if (has_l) s.vl = __ldg(p - 1);
                if (has_r) s.vr = __ldg(p + 4);
            }
            return s;
        };

        // Horizontal 3-sums of w=exp(-v) and wv for one row (pure compute).
        auto hsum = [&](const Slot& s, float4& w, float4& wv) {
            const float w0 = __expf(-s.v.x);
            const float w1 = __expf(-s.v.y);
            const float w2 = __expf(-s.v.z);
            const float w3 = __expf(-s.v.w);
            const float wl = __expf(-s.vl);
            const float wr = __expf(-s.vr);
            w.x = wl + w0 + w1;
            w.y = w0 + w1 + w2;
            w.z = w1 + w2 + w3;
            w.w = w2 + w3 + wr;
            const float al = wl * s.vl,  a0 = w0 * s.v.x, a1 = w1 * s.v.y;
            const float a2 = w2 * s.v.z, a3 = w3 * s.v.w, ar = wr * s.vr;
            wv.x = al + a0 + a1;
            wv.y = a0 + a1 + a2;
            wv.z = a1 + a2 + a3;
            wv.w = a2 + a3 + ar;
        };

        // Prologue. slot(row) = (row - y0 + 2) % 3.
        Slot s_m1 = loadrow(y0 - 1);
        Slot s_0  = loadrow(y0);
        ring[0] = loadrow(y0 + 1);   // row y0+1 -> slot 0
        ring[1] = loadrow(y0 + 2);   // row y0+2 -> slot 1

        float4 hw0, hv0, hw1, hv1;
        hsum(s_m1, hw0, hv0);
        hsum(s_0,  hw1, hv1);
        float4 Aw  = f4add(hw0, hw1), Bw  = hw1;   // A = h(-1)+h(0), B = h(0)
        float4 Awv = f4add(hv0, hv1), Bwv = hv1;

        #pragma unroll
        for (int k = 0; k < SROWS; k++) {
            // Prefetch row y0+k+3 into slot (k+2)%3 (freed: row y0+k consumed
            // at k-1). Live rows k+1..k+3 occupy the 3 slots.
            if (k < SROWS - 2)
                ring[(k + 2) % 3] = loadrow(y0 + k + 3);
            // Consume row y0+k+1 (slot k%3), loaded 2 iterations ago.
            float4 hw, hv;
            hsum(ring[k % 3], hw, hv);

            const float4 den = f4add(Aw,  hw);
            const float4 num = f4add(Awv, hv);
            float4 o;
            o.x = __fdividef(num.x, den.x);
            o.y = __fdividef(num.y, den.y);
            o.z = __fdividef(num.z, den.z);
            o.w = __fdividef(num.w, den.w);
            __stcs(reinterpret_cast<float4*>(optr), o);
            optr += IMG_W;

            Aw  = f4add(Bw,  hw);  Bw  = hw;
            Awv = f4add(Bwv, hv);  Bwv = hv;
        }
    }
}

extern "C" void kernel_launch(void* const* d_in, const int* in_sizes, int n_in,
                              void* d_out, int out_size) {
    const float* x = (const float*)d_in[0];
    float* out = (float*)d_out;
    wavg_kernel<<<NBLK, WPB * 32>>>(x, out);
}